// round 8
// baseline (speedup 1.0000x reference)
// QLSTM: quantum-gate LSTM, T=2048, B=256, D=128, H=NQ=4.
//
// Kernel 1 (qlstm_gemm): pre[t,b,16] = x[t,b,:]@W_g[:128,:] + b_g + theta_g
// Kernel 2 (qlstm_scan): serial recurrence, PAIR layout: 2 lanes per batch
//   element. half 0 owns gates {forget,input}, half 1 owns {update,output}.
//   One shfl.xor partner exchange per step; both lanes then redundantly
//   compute the full (bitwise-identical) c/h joint update.
//
// qlayer(x, theta) = cumprod(cos(x + theta)); theta/bias folded into pre.
// Gate activations via MUFU.TANH; tanh(c) via ex2+rcp (error-critical path).

#include <cuda_runtime.h>
#include <cstdint>

#define TT 2048
#define BB 256
#define DD 128
#define ROWS (TT * BB)   // 524288

// scratch: pre-activations [T][B][16] + 2 timesteps of padding so the scan's
// prefetch (t+2) never needs a clamp.
__device__ __align__(128) float g_pre[(TT + 2) * BB * 16];

// ---------------------------------------------------------------------------
// math helpers
// ---------------------------------------------------------------------------
__device__ __forceinline__ float tanh_hw(float x) {          // MUFU.TANH
    float r;
    asm("tanh.approx.f32 %0, %1;" : "=f"(r) : "f"(x));
    return r;
}
__device__ __forceinline__ float rcp_fast(float x) {         // MUFU.RCP
    float r;
    asm("rcp.approx.f32 %0, %1;" : "=f"(r) : "f"(x));
    return r;
}
__device__ __forceinline__ float ex2_fast(float x) {         // MUFU.EX2
    float r;
    asm("ex2.approx.f32 %0, %1;" : "=f"(r) : "f"(x));
    return r;
}
// precise-ish tanh via exp2: tanh(x) = 1 - 2/(1 + e^{2x}); |x| <= ~2.8 here.
__device__ __forceinline__ float tanh_exp(float x) {
    float e = ex2_fast(x * 2.8853900817779268f);  // 2*log2(e)
    float r = rcp_fast(e + 1.0f);
    return fmaf(-2.0f, r, 1.0f);
}

// f32x2 packed helpers (Blackwell)
__device__ __forceinline__ unsigned long long pk2(float lo, float hi) {
    unsigned long long r;
    asm("mov.b64 %0, {%1, %2};" : "=l"(r) : "f"(lo), "f"(hi));
    return r;
}
__device__ __forceinline__ void upk2(unsigned long long v, float& lo, float& hi) {
    asm("mov.b64 {%0, %1}, %2;" : "=f"(lo), "=f"(hi) : "l"(v));
}
__device__ __forceinline__ unsigned long long fma2(unsigned long long a,
                                                   unsigned long long b,
                                                   unsigned long long c) {
    unsigned long long d;
    asm("fma.rn.f32x2 %0, %1, %2, %3;" : "=l"(d) : "l"(a), "l"(b), "l"(c));
    return d;
}

// ---------------------------------------------------------------------------
// Kernel 1: pre[row][g*4+k] = sum_j x[row][j]*W_g[j][k] + b_g[k] + theta_g[k]
// Block: 128 threads, tile = 64 rows x 128 cols in smem, f32x2 accumulators.
// ---------------------------------------------------------------------------
__global__ __launch_bounds__(128) void qlstm_gemm(
    const float* __restrict__ x,
    const float* __restrict__ W0, const float* __restrict__ b0, const float* __restrict__ q0,
    const float* __restrict__ W1, const float* __restrict__ b1, const float* __restrict__ q1,
    const float* __restrict__ W2, const float* __restrict__ b2, const float* __restrict__ q2,
    const float* __restrict__ W3, const float* __restrict__ b3, const float* __restrict__ q3)
{
    __shared__ __align__(16) float xs[64 * 132];
    __shared__ __align__(16) float ws[128 * 16];
    __shared__ float bt[16];

    int tid = threadIdx.x;

    for (int idx = tid; idx < 2048; idx += 128) {
        int j = idx >> 4, c = idx & 15, gg = c >> 2, k = c & 3;
        const float* W = (gg == 0) ? W0 : (gg == 1) ? W1 : (gg == 2) ? W2 : W3;
        ws[j * 16 + c] = W[j * 4 + k];
    }
    if (tid < 16) {
        int gg = tid >> 2, k = tid & 3;
        const float* bb = (gg == 0) ? b0 : (gg == 1) ? b1 : (gg == 2) ? b2 : b3;
        const float* qq = (gg == 0) ? q0 : (gg == 1) ? q1 : (gg == 2) ? q2 : q3;
        bt[tid] = bb[k] + qq[k];
    }

    size_t row0 = (size_t)blockIdx.x * 64;
    const float4* xin = (const float4*)x + row0 * 32;
    #pragma unroll
    for (int i = 0; i < 16; i++) {
        int idx = tid + i * 128;
        int fr = idx >> 5, c4 = idx & 31;
        float4 v = xin[idx];
        *(float4*)&xs[fr * 132 + c4 * 4] = v;
    }
    __syncthreads();

    int row = tid >> 1;
    int kb = (tid & 1) * 8;

    unsigned long long acc[4];
    #pragma unroll
    for (int p = 0; p < 4; p++)
        acc[p] = pk2(bt[kb + 2 * p], bt[kb + 2 * p + 1]);

    #pragma unroll 4
    for (int j = 0; j < 128; j += 4) {
        float4 xv = *(const float4*)&xs[row * 132 + j];
        float xr[4] = {xv.x, xv.y, xv.z, xv.w};
        #pragma unroll
        for (int jj = 0; jj < 4; jj++) {
            unsigned long long xp = pk2(xr[jj], xr[jj]);
            const ulonglong2* wp = (const ulonglong2*)&ws[(j + jj) * 16 + kb];
            ulonglong2 wa = wp[0];
            ulonglong2 wb = wp[1];
            acc[0] = fma2(xp, wa.x, acc[0]);
            acc[1] = fma2(xp, wa.y, acc[1]);
            acc[2] = fma2(xp, wb.x, acc[2]);
            acc[3] = fma2(xp, wb.y, acc[3]);
        }
    }

    float4 r0, r1;
    upk2(acc[0], r0.x, r0.y);
    upk2(acc[1], r0.z, r0.w);
    upk2(acc[2], r1.x, r1.y);
    upk2(acc[3], r1.z, r1.w);
    float4* dst = (float4*)&g_pre[(row0 + row) * 16 + kb];
    dst[0] = r0;
    dst[1] = r1;
}

// ---------------------------------------------------------------------------
// Kernel 2: serial scan, PAIR layout. 16 blocks x 32 threads.
// lane = (local_elem << 1) | half; half 0 -> gates {0:forget, 1:input},
// half 1 -> gates {2:update, 3:output}. Slot A = gate 2*half, slot B = 2*half+1.
// ---------------------------------------------------------------------------
__global__ __launch_bounds__(32) void qlstm_scan(
    const float* __restrict__ W0, const float* __restrict__ W1,
    const float* __restrict__ W2, const float* __restrict__ W3,
    float* __restrict__ out)
{
    const unsigned FULL = 0xffffffffu;
    int lane = threadIdx.x;
    int half = lane & 1;
    int b    = (int)blockIdx.x * 16 + (lane >> 1);

    // recurrent weights for this lane's two gates, packed f32x2
    const float* WA = half ? W2 : W0;   // slot A: forget (h0) / update (h1)
    const float* WB = half ? W3 : W1;   // slot B: input  (h0) / output (h1)
    unsigned long long wA[4][2], wB[4][2];
    #pragma unroll
    for (int j = 0; j < 4; j++) {
        wA[j][0] = pk2(WA[(DD + j) * 4 + 0], WA[(DD + j) * 4 + 1]);
        wA[j][1] = pk2(WA[(DD + j) * 4 + 2], WA[(DD + j) * 4 + 3]);
        wB[j][0] = pk2(WB[(DD + j) * 4 + 0], WB[(DD + j) * 4 + 1]);
        wB[j][1] = pk2(WB[(DD + j) * 4 + 2], WB[(DD + j) * 4 + 3]);
    }

    // slot A activation: half0 -> sigmoid, half1 -> tanh. slot B: always sigmoid.
    float pmA  = half ? 1.0f : 0.5f;
    float abA  = half ? 0.0f : 0.5f;
    float ascA = half ? 1.0f : 0.5f;

    float h0 = 0.f, h1 = 0.f, h2 = 0.f, h3 = 0.f;
    float c0 = 0.f, c1 = 0.f, c2 = 0.f, c3 = 0.f;

    // pre[t][b][half*8 .. half*8+7] as 2x float4; per-t stride = 1024 float4s.
    const float4* pp = (const float4*)g_pre + (size_t)b * 4 + half * 2;
    float4 curA = pp[0],    curB = pp[1];
    float4 nxtA = pp[1024], nxtB = pp[1025];
    pp += 2048;
    // output: lane stores its half's 2 components (float2), warp-contiguous
    float2* op = (float2*)(out + (size_t)b * 4 + half * 2);

    #pragma unroll 2
    for (int t = 0; t < TT; t++) {
        float4 zA4 = curA, zB4 = curB;
        curA = nxtA; curB = nxtB;
        nxtA = pp[0]; nxtB = pp[1];    // L2-resident prefetch, 2 steps ahead
        pp += 1024;

        // z = pre + h @ Wh for both owned gates (packed f32x2)
        unsigned long long zA01 = pk2(zA4.x, zA4.y), zA23 = pk2(zA4.z, zA4.w);
        unsigned long long zB01 = pk2(zB4.x, zB4.y), zB23 = pk2(zB4.z, zB4.w);
        unsigned long long hp;
        hp = pk2(h0, h0);
        zA01 = fma2(hp, wA[0][0], zA01); zA23 = fma2(hp, wA[0][1], zA23);
        zB01 = fma2(hp, wB[0][0], zB01); zB23 = fma2(hp, wB[0][1], zB23);
        hp = pk2(h1, h1);
        zA01 = fma2(hp, wA[1][0], zA01); zA23 = fma2(hp, wA[1][1], zA23);
        zB01 = fma2(hp, wB[1][0], zB01); zB23 = fma2(hp, wB[1][1], zB23);
        hp = pk2(h2, h2);
        zA01 = fma2(hp, wA[2][0], zA01); zA23 = fma2(hp, wA[2][1], zA23);
        zB01 = fma2(hp, wB[2][0], zB01); zB23 = fma2(hp, wB[2][1], zB23);
        hp = pk2(h3, h3);
        zA01 = fma2(hp, wA[3][0], zA01); zA23 = fma2(hp, wA[3][1], zA23);
        zB01 = fma2(hp, wB[3][0], zB01); zB23 = fma2(hp, wB[3][1], zB23);

        float zA0, zA1, zA2, zA3, zB0, zB1, zB2, zB3;
        upk2(zA01, zA0, zA1); upk2(zA23, zA2, zA3);
        upk2(zB01, zB0, zB1); upk2(zB23, zB2, zB3);

        // qlayer: cumprod of cosines, both gates (independent chains -> ILP)
        float qA0 = __cosf(zA0), qA1 = __cosf(zA1), qA2 = __cosf(zA2), qA3 = __cosf(zA3);
        float qB0 = __cosf(zB0), qB1 = __cosf(zB1), qB2 = __cosf(zB2), qB3 = __cosf(zB3);
        float mA = qA0 * qA1, nA = qA2 * qA3;
        float mB = qB0 * qB1, nB = qB2 * qB3;
        float pA0 = qA0, pA1 = mA, pA2 = mA * qA2, pA3 = mA * nA;
        float pB0 = qB0, pB1 = mB, pB2 = mB * qB2, pB3 = mB * nB;

        // activations (MUFU.TANH)
        float aA0 = fmaf(ascA, tanh_hw(pmA * pA0), abA);
        float aA1 = fmaf(ascA, tanh_hw(pmA * pA1), abA);
        float aA2 = fmaf(ascA, tanh_hw(pmA * pA2), abA);
        float aA3 = fmaf(ascA, tanh_hw(pmA * pA3), abA);
        float aB0 = fmaf(0.5f, tanh_hw(0.5f * pB0), 0.5f);
        float aB1 = fmaf(0.5f, tanh_hw(0.5f * pB1), 0.5f);
        float aB2 = fmaf(0.5f, tanh_hw(0.5f * pB2), 0.5f);
        float aB3 = fmaf(0.5f, tanh_hw(0.5f * pB3), 0.5f);

        // partner exchange: 8 shfl.xor (single round)
        float rA0 = __shfl_xor_sync(FULL, aA0, 1);
        float rA1 = __shfl_xor_sync(FULL, aA1, 1);
        float rA2 = __shfl_xor_sync(FULL, aA2, 1);
        float rA3 = __shfl_xor_sync(FULL, aA3, 1);
        float rB0 = __shfl_xor_sync(FULL, aB0, 1);
        float rB1 = __shfl_xor_sync(FULL, aB1, 1);
        float rB2 = __shfl_xor_sync(FULL, aB2, 1);
        float rB3 = __shfl_xor_sync(FULL, aB3, 1);

        // canonicalize roles (branch-free SELs); values identical across pair
        bool h1p = (half != 0);
        float f0 = h1p ? rA0 : aA0, f1 = h1p ? rA1 : aA1;
        float f2 = h1p ? rA2 : aA2, f3 = h1p ? rA3 : aA3;
        float i0 = h1p ? rB0 : aB0, i1 = h1p ? rB1 : aB1;
        float i2 = h1p ? rB2 : aB2, i3 = h1p ? rB3 : aB3;
        float u0 = h1p ? aA0 : rA0, u1 = h1p ? aA1 : rA1;
        float u2 = h1p ? aA2 : rA2, u3 = h1p ? aA3 : rA3;
        float o0 = h1p ? aB0 : rB0, o1 = h1p ? aB1 : rB1;
        float o2 = h1p ? aB2 : rB2, o3 = h1p ? aB3 : rB3;

        // joint update, identical in both lanes of the pair
        c0 = fmaf(f0, c0, i0 * u0);
        c1 = fmaf(f1, c1, i1 * u1);
        c2 = fmaf(f2, c2, i2 * u2);
        c3 = fmaf(f3, c3, i3 * u3);

        h0 = o0 * tanh_exp(c0);
        h1 = o1 * tanh_exp(c1);
        h2 = o2 * tanh_exp(c2);
        h3 = o3 * tanh_exp(c3);

        // branch-free store: each lane stores its half's pair (STG.64)
        float s0 = h1p ? h2 : h0;
        float s1 = h1p ? h3 : h1;
        *op = make_float2(s0, s1);
        op += BB * 2;   // advance one timestep (1024 floats = 512 float2)
    }

    // trailing hx / cx blocks of the tuple output
    {
        bool h1p = (half != 0);
        float s0 = h1p ? h2 : h0;
        float s1 = h1p ? h3 : h1;
        float t0 = h1p ? c2 : c0;
        float t1 = h1p ? c3 : c1;
        float2* hxp = (float2*)(out + (size_t)TT * BB * 4 + (size_t)b * 4 + half * 2);
        float2* cxp = (float2*)(out + (size_t)TT * BB * 4 + (size_t)BB * 4 + (size_t)b * 4 + half * 2);
        *hxp = make_float2(s0, s1);
        *cxp = make_float2(t0, t1);
    }
}

// ---------------------------------------------------------------------------
extern "C" void kernel_launch(void* const* d_in, const int* in_sizes, int n_in,
                              void* d_out, int out_size) {
    const float* x  = (const float*)d_in[0];
    const float* Wf = (const float*)d_in[1];
    const float* bf = (const float*)d_in[2];
    const float* qf = (const float*)d_in[3];
    const float* Wi = (const float*)d_in[4];
    const float* bi = (const float*)d_in[5];
    const float* qi = (const float*)d_in[6];
    const float* Wu = (const float*)d_in[7];
    const float* bu = (const float*)d_in[8];
    const float* qu = (const float*)d_in[9];
    const float* Wo = (const float*)d_in[10];
    const float* bo = (const float*)d_in[11];
    const float* qo = (const float*)d_in[12];

    qlstm_gemm<<<ROWS / 64, 128>>>(x, Wf, bf, qf, Wi, bi, qi, Wu, bu, qu, Wo, bo, qo);
    qlstm_scan<<<BB / 16, 32>>>(Wf, Wi, Wu, Wo, (float*)d_out);
}